// round 10
// baseline (speedup 1.0000x reference)
#include <cuda_runtime.h>
#include <math.h>

#define CIN      16
#define COUT     32
#define KDIM     1024             // 64 taps * 16 cin
#define VPT      16               // voxels per tile
#define THREADS  256
#define A_STRIDE 1028             // 1024 + 4 pad
#define N_TILES  6250             // 100000 / 16
#define GRID     152

// smem layout (floats):
//  A_s[2]  : 2 * VPT * A_STRIDE   (131584 B)
//  P_s     : 4 * VPT * COUT       (  8192 B)
//  St4_s   : 4 pwarps * 64 * 4    (  4096 B)
//  Aux_s   : 4 pwarps * 64        (  1024 B)
//  den_s   : 2 * VPT              (   128 B)
#define SMEM_FLOATS (2 * VPT * A_STRIDE + 4 * VPT * COUT + 4 * 64 * 4 + 4 * 64 + 2 * VPT)

extern __shared__ float smem[];

__global__ void __launch_bounds__(THREADS, 1)
cconv_kernel(const float* __restrict__ feats,
             const float* __restrict__ inp_points,
             const float* __restrict__ out_points,
             const float* __restrict__ out_extents,
             const float* __restrict__ scale_compat,
             const float* __restrict__ nbr_dist,
             const int*   __restrict__ nbr_idx,
             const int*   __restrict__ row_splits,
             const float* __restrict__ Wg,
             const float* __restrict__ bias,
             float*       __restrict__ out,
             int n_out, int n_edges)
{
    float*  A0    = smem;                                 // buf 0
    float*  A1    = smem + VPT * A_STRIDE;                // buf 1
    float*  P_s   = smem + 2 * VPT * A_STRIDE;
    float4* St4_s = reinterpret_cast<float4*>(P_s + 4 * VPT * COUT);
    unsigned int* Aux_s = reinterpret_cast<unsigned int*>(P_s + 4 * VPT * COUT + 4 * 64 * 4);
    float*  den_s = reinterpret_cast<float*>(Aux_s + 4 * 64);   // [2][VPT]

    const int tid  = threadIdx.x;
    const int warp = tid >> 5;
    const int lane = tid & 31;
    const bool is_prod = (warp < 4);

    // number of tiles this block owns (strided assignment)
    int nt = 0;
    for (int t = blockIdx.x; t < N_TILES; t += GRID) ++nt;

    // consumer constants (R6 phase-2 tiling, k-slice 256)
    const int cw    = warp - 4;
    const int kbase = cw * 256;
    const int vq    = lane & 3;
    const int cq    = lane >> 2;
    const int ctid  = tid - 128;          // 0..127 for consumers
    const int rvv   = ctid >> 3;          // reduce: voxel 0..15
    const int rc0   = (ctid & 7) * 4;     // reduce: cout group
    float4 bias4 = make_float4(0.f, 0.f, 0.f, 0.f);
    if (!is_prod) bias4 = *reinterpret_cast<const float4*>(bias + rc0);

    // producer constants
    const int pw    = warp;               // producer warp id 0..3
    const int vhalf = lane >> 4;
    const int le    = lane & 15;
    const int ch    = lane & 15;
    const int chalf = lane >> 4;
    float4*       myst  = St4_s + pw * 64;
    unsigned int* myaux = Aux_s + pw * 64;

    for (int it = 0; it <= nt; ++it) {
        if (is_prod && it < nt) {
            // ================= PRODUCER: fill buf[it&1] with tile(it) ========
            const int tile = blockIdx.x + it * GRID;
            float* Ab = (it & 1) ? A1 : A0;
            float* db = den_s + (it & 1) * VPT;

            // zero this warp's 4 acc rows
            {
                float4* acc4 = reinterpret_cast<float4*>(Ab + (pw * 4) * A_STRIDE);
                #pragma unroll
                for (int i = 0; i < 32; ++i)
                    acc4[lane + i * 32] = make_float4(0.f, 0.f, 0.f, 0.f);
                if (lane < 16) (Ab + (pw * 4) * A_STRIDE)[4096 + lane] = 0.f;
            }

            // geometry: 2 passes, 2 voxels per pass (half-warp each)
            #pragma unroll
            for (int pass = 0; pass < 2; ++pass) {
                const int vloc = pw * 4 + pass * 2 + vhalf;
                const int v    = tile * VPT + vloc;

                float imp_l = 0.f, f0_l = 0.f, f1_l = 0.f, f2_l = 0.f;
                unsigned int aux_l = 0;
                int e0 = 0, cnt = 0;
                if (v < n_out) {
                    e0  = row_splits[v];
                    cnt = row_splits[v + 1] - e0;
                    const float ox = out_points[v * 3 + 0];
                    const float oy = out_points[v * 3 + 1];
                    const float oz = out_points[v * 3 + 2];
                    const float inv_r = 2.0f / out_extents[v];

                    int e = e0 + le;
                    if (e >= n_edges) e = n_edges - 1;

                    const float sc = scale_compat[e];
                    const float d  = nbr_dist[e];
                    float omr = 1.0f - d;
                    float w6  = omr * omr * omr;
                    w6 = fminf(fmaxf(w6, 0.0f), 1.0f);

                    const int nb = nbr_idx[e];
                    const float rx = (inp_points[nb * 3 + 0] - ox) * inv_r;
                    const float ry = (inp_points[nb * 3 + 1] - oy) * inv_r;
                    const float rz = (inp_points[nb * 3 + 2] - oz) * inv_r;

                    const float l2   = sqrtf(rx * rx + ry * ry + rz * rz);
                    const float linf = fmaxf(fabsf(rx), fmaxf(fabsf(ry), fabsf(rz)));
                    const float s    = (linf > 0.0f) ? (l2 / fmaxf(linf, 1e-12f)) : 0.0f;

                    const float q0 = fminf(fmaxf(rx * s, -1.0f), 1.0f);
                    const float q1 = fminf(fmaxf(ry * s, -1.0f), 1.0f);
                    const float q2 = fminf(fmaxf(rz * s, -1.0f), 1.0f);

                    const float t0 = (q0 + 1.0f) * 1.5f;
                    const float t1 = (q1 + 1.0f) * 1.5f;
                    const float t2 = (q2 + 1.0f) * 1.5f;

                    const float fl0 = fminf(fmaxf(floorf(t0), 0.0f), 2.0f);
                    const float fl1 = fminf(fmaxf(floorf(t1), 0.0f), 2.0f);
                    const float fl2 = fminf(fmaxf(floorf(t2), 0.0f), 2.0f);
                    f0_l = t0 - fl0;
                    f1_l = t1 - fl1;
                    f2_l = t2 - fl2;
                    const int cb = (((int)fl0) * 4 + (int)fl1) * 4 + (int)fl2;

                    imp_l = (le < cnt) ? (sc * w6) : 0.f;
                    aux_l = ((unsigned int)cb << 18) | (unsigned int)nb;
                }
                myst[pass * 32 + lane]  = make_float4(imp_l, f0_l, f1_l, f2_l);
                myaux[pass * 32 + lane] = aux_l;

                float den = imp_l;
                #pragma unroll
                for (int off = 8; off > 0; off >>= 1)
                    den += __shfl_xor_sync(0xffffffffu, den, off);
                if (le == 0) db[vloc] = (den != 0.0f) ? den : 1.0f;
            }
            __syncwarp();

            // scatter: 4 voxels
            #pragma unroll
            for (int vi = 0; vi < 4; ++vi) {
                float* acc = Ab + (pw * 4 + vi) * A_STRIDE;
                const int ebase = vi * 16;

                unsigned int auxr[16];
                float fv[16];
                #pragma unroll
                for (int e = 0; e < 16; ++e) {
                    auxr[e] = myaux[ebase + e];
                    fv[e] = feats[(auxr[e] & 0x3FFFFu) * CIN + ch];
                }

                #pragma unroll
                for (int e = 0; e < 16; ++e) {
                    const float4 g = myst[ebase + e];
                    const float psi = g.x * fv[e];
                    const int   cb  = (int)(auxr[e] >> 18);
                    const float g0 = 1.0f - g.y, g1 = 1.0f - g.z, g2 = 1.0f - g.w;

                    #pragma unroll
                    for (int cc = 0; cc < 4; ++cc) {
                        const int c  = cc * 2 + chalf;
                        const int cz = (c >> 2) & 1;
                        const int cy = (c >> 1) & 1;
                        const int cx = c & 1;
                        const float w = (cz ? g.y : g0) * (cy ? g.z : g1) * (cx ? g.w : g2);
                        const int corner = cb + cz * 16 + cy * 4 + cx;
                        acc[corner * CIN + ch] += w * psi;
                    }
                }
            }
        } else if (!is_prod && it >= 1) {
            // ================= CONSUMER: GEMM tile(it-1) from buf[(it-1)&1] ==
            const int tile = blockIdx.x + (it - 1) * GRID;
            const float* Ab = ((it - 1) & 1) ? A1 : A0;
            const float* db = den_s + ((it - 1) & 1) * VPT;

            const float* Wp = Wg + kbase * COUT + cq * 4;

            float acc[4][4];
            #pragma unroll
            for (int i = 0; i < 4; ++i)
                #pragma unroll
                for (int j = 0; j < 4; ++j) acc[i][j] = 0.f;

            float4 af[2][4], wf[2][4];
            #pragma unroll
            for (int i = 0; i < 4; ++i)
                af[0][i] = *reinterpret_cast<const float4*>(Ab + (vq + 4 * i) * A_STRIDE + kbase);
            #pragma unroll
            for (int j = 0; j < 4; ++j)
                wf[0][j] = *reinterpret_cast<const float4*>(Wp + j * COUT);

            #pragma unroll 2
            for (int kc = 0; kc < 64; ++kc) {
                const int cur = kc & 1;
                const int nxt = cur ^ 1;
                if (kc < 63) {
                    const int koff = (kc + 1) * 4;
                    #pragma unroll
                    for (int i = 0; i < 4; ++i)
                        af[nxt][i] = *reinterpret_cast<const float4*>(Ab + (vq + 4 * i) * A_STRIDE + kbase + koff);
                    #pragma unroll
                    for (int j = 0; j < 4; ++j)
                        wf[nxt][j] = *reinterpret_cast<const float4*>(Wp + (koff + j) * COUT);
                }
                #pragma unroll
                for (int i = 0; i < 4; ++i) {
                    const float4 a = af[cur][i];
                    acc[i][0] = fmaf(a.x, wf[cur][0].x, acc[i][0]);
                    acc[i][1] = fmaf(a.x, wf[cur][0].y, acc[i][1]);
                    acc[i][2] = fmaf(a.x, wf[cur][0].z, acc[i][2]);
                    acc[i][3] = fmaf(a.x, wf[cur][0].w, acc[i][3]);
                    acc[i][0] = fmaf(a.y, wf[cur][1].x, acc[i][0]);
                    acc[i][1] = fmaf(a.y, wf[cur][1].y, acc[i][1]);
                    acc[i][2] = fmaf(a.y, wf[cur][1].z, acc[i][2]);
                    acc[i][3] = fmaf(a.y, wf[cur][1].w, acc[i][3]);
                    acc[i][0] = fmaf(a.z, wf[cur][2].x, acc[i][0]);
                    acc[i][1] = fmaf(a.z, wf[cur][2].y, acc[i][1]);
                    acc[i][2] = fmaf(a.z, wf[cur][2].z, acc[i][2]);
                    acc[i][3] = fmaf(a.z, wf[cur][2].w, acc[i][3]);
                    acc[i][0] = fmaf(a.w, wf[cur][3].x, acc[i][0]);
                    acc[i][1] = fmaf(a.w, wf[cur][3].y, acc[i][1]);
                    acc[i][2] = fmaf(a.w, wf[cur][3].z, acc[i][2]);
                    acc[i][3] = fmaf(a.w, wf[cur][3].w, acc[i][3]);
                }
            }

            #pragma unroll
            for (int i = 0; i < 4; ++i) {
                const int vv = vq + 4 * i;
                *reinterpret_cast<float4*>(P_s + (cw * VPT + vv) * COUT + cq * 4) =
                    make_float4(acc[i][0], acc[i][1], acc[i][2], acc[i][3]);
            }

            // consumer-group barrier, then reduce 4 partials + store
            asm volatile("bar.sync 1, 128;" ::: "memory");

            float4 s = make_float4(0.f, 0.f, 0.f, 0.f);
            #pragma unroll
            for (int w = 0; w < 4; ++w) {
                const float4 p = *reinterpret_cast<const float4*>(P_s + (w * VPT + rvv) * COUT + rc0);
                s.x += p.x; s.y += p.y; s.z += p.z; s.w += p.w;
            }
            const int vg = tile * VPT + rvv;
            if (vg < n_out) {
                const float inv_den = 1.0f / db[rvv];
                float4 r;
                r.x = fmaxf(s.x * inv_den + bias4.x, 0.0f);
                r.y = fmaxf(s.y * inv_den + bias4.y, 0.0f);
                r.z = fmaxf(s.z * inv_den + bias4.z, 0.0f);
                r.w = fmaxf(s.w * inv_den + bias4.w, 0.0f);
                *reinterpret_cast<float4*>(out + vg * COUT + rc0) = r;
            }
            // bar 1 again so no consumer warp races ahead into next tile's P_s
            asm volatile("bar.sync 1, 128;" ::: "memory");
        }

        __syncthreads();
    }
}

extern "C" void kernel_launch(void* const* d_in, const int* in_sizes, int n_in,
                              void* d_out, int out_size)
{
    const float* feats        = (const float*)d_in[0];
    const float* inp_points   = (const float*)d_in[1];
    const float* out_points   = (const float*)d_in[2];
    const float* out_extents  = (const float*)d_in[3];
    const float* scale_compat = (const float*)d_in[4];
    const float* nbr_dist     = (const float*)d_in[5];
    const int*   nbr_idx      = (const int*)d_in[6];
    const int*   row_splits   = (const int*)d_in[7];
    const float* Wg           = (const float*)d_in[8];
    const float* bias         = (const float*)d_in[9];
    float*       out          = (float*)d_out;

    const int n_out   = in_sizes[7] - 1;
    const int n_edges = in_sizes[6];

    const size_t smem_bytes = SMEM_FLOATS * sizeof(float);
    cudaFuncSetAttribute(cconv_kernel,
                         cudaFuncAttributeMaxDynamicSharedMemorySize,
                         (int)smem_bytes);

    cconv_kernel<<<GRID, THREADS, smem_bytes>>>(
        feats, inp_points, out_points, out_extents, scale_compat,
        nbr_dist, nbr_idx, row_splits, Wg, bias, out, n_out, n_edges);
}

// round 11
// speedup vs baseline: 1.1239x; 1.1239x over previous
#include <cuda_runtime.h>
#include <math.h>

#define CIN      16
#define COUT     32
#define KDIM     1024             // 64 taps * 16 cin
#define VPB      12               // voxels per block (3 blocks/SM)
#define THREADS  256
#define A_STRIDE 1028             // 1024 + 4 pad (rows offset by 4 banks)

// dynamic smem layout:
//  A_s   : VPB * A_STRIDE floats            (49344 B)
//  P_s   : 8 * VPB * COUT floats            (12288 B)
//  St4_s : 6 pwarps * 32 edges * float4     ( 3072 B)
//  Aux_s : 6 pwarps * 32 edges * uint       (  768 B)
//  den_s : VPB floats                       (   48 B)
#define SMEM_FLOATS (VPB * A_STRIDE + 8 * VPB * COUT + 6 * 32 * 4 + 6 * 32 + VPB)

extern __shared__ float smem[];

__global__ void __launch_bounds__(THREADS, 3)
cconv_kernel(const float* __restrict__ feats,
             const float* __restrict__ inp_points,
             const float* __restrict__ out_points,
             const float* __restrict__ out_extents,
             const float* __restrict__ scale_compat,
             const float* __restrict__ nbr_dist,
             const int*   __restrict__ nbr_idx,
             const int*   __restrict__ row_splits,
             const float* __restrict__ Wg,
             const float* __restrict__ bias,
             float*       __restrict__ out,
             int n_out, int n_edges)
{
    float*  A_s   = smem;
    float*  P_s   = A_s + VPB * A_STRIDE;
    float4* St4_s = reinterpret_cast<float4*>(P_s + 8 * VPB * COUT);
    unsigned int* Aux_s = reinterpret_cast<unsigned int*>(P_s + 8 * VPB * COUT + 6 * 32 * 4);
    float*  den_s = reinterpret_cast<float*>(Aux_s + 6 * 32);

    const int tid  = threadIdx.x;
    const int warp = tid >> 5;
    const int lane = tid & 31;

    // ---- phase 1 (warps 0..5): 2 voxels per warp ----
    if (warp < 6) {
        float4*       myst  = St4_s + warp * 32;
        unsigned int* myaux = Aux_s + warp * 32;

        // zero both acc rows owned by this warp
        {
            float4* acc4 = reinterpret_cast<float4*>(A_s + (warp * 2) * A_STRIDE);
            #pragma unroll
            for (int i = 0; i < 16; ++i)
                acc4[lane + i * 32] = make_float4(0.f, 0.f, 0.f, 0.f);
            if (lane < 8) (A_s + (warp * 2) * A_STRIDE)[2048 + lane] = 0.f;
        }

        // -- phase 1a: geometry for BOTH voxels in parallel (half-warp each) --
        const int vhalf = lane >> 4;           // 0 = voxel A, 1 = voxel B
        const int le    = lane & 15;           // edge slot within voxel
        const int vloc  = warp * 2 + vhalf;
        const int v     = blockIdx.x * VPB + vloc;

        float imp_l = 0.f, f0_l = 0.f, f1_l = 0.f, f2_l = 0.f;
        unsigned int aux_l = 0;
        {
            int e0 = 0, cnt = 0;
            if (v < n_out) {
                e0  = row_splits[v];
                cnt = row_splits[v + 1] - e0;
            }
            const bool act = (le < cnt);
            if (v < n_out) {
                const float ox = out_points[v * 3 + 0];
                const float oy = out_points[v * 3 + 1];
                const float oz = out_points[v * 3 + 2];
                const float inv_r = 2.0f / out_extents[v];

                int e = e0 + le;
                if (e >= n_edges) e = n_edges - 1;

                const float sc = scale_compat[e];
                const float d  = nbr_dist[e];
                float omr = 1.0f - d;
                float w6  = omr * omr * omr;
                w6 = fminf(fmaxf(w6, 0.0f), 1.0f);

                const int nb = nbr_idx[e];
                const float rx = (inp_points[nb * 3 + 0] - ox) * inv_r;
                const float ry = (inp_points[nb * 3 + 1] - oy) * inv_r;
                const float rz = (inp_points[nb * 3 + 2] - oz) * inv_r;

                const float l2   = sqrtf(rx * rx + ry * ry + rz * rz);
                const float linf = fmaxf(fabsf(rx), fmaxf(fabsf(ry), fabsf(rz)));
                const float s    = (linf > 0.0f) ? (l2 / fmaxf(linf, 1e-12f)) : 0.0f;

                const float q0 = fminf(fmaxf(rx * s, -1.0f), 1.0f);
                const float q1 = fminf(fmaxf(ry * s, -1.0f), 1.0f);
                const float q2 = fminf(fmaxf(rz * s, -1.0f), 1.0f);

                const float t0 = (q0 + 1.0f) * 1.5f;
                const float t1 = (q1 + 1.0f) * 1.5f;
                const float t2 = (q2 + 1.0f) * 1.5f;

                const float fl0 = fminf(fmaxf(floorf(t0), 0.0f), 2.0f);
                const float fl1 = fminf(fmaxf(floorf(t1), 0.0f), 2.0f);
                const float fl2 = fminf(fmaxf(floorf(t2), 0.0f), 2.0f);
                f0_l = t0 - fl0;
                f1_l = t1 - fl1;
                f2_l = t2 - fl2;
                const int cb = (((int)fl0) * 4 + (int)fl1) * 4 + (int)fl2;

                imp_l = act ? (sc * w6) : 0.f;
                aux_l = ((unsigned int)cb << 18) | (unsigned int)nb;
            }
        }
        myst[lane]  = make_float4(imp_l, f0_l, f1_l, f2_l);
        myaux[lane] = aux_l;

        {
            float den = imp_l;
            #pragma unroll
            for (int off = 8; off > 0; off >>= 1)
                den += __shfl_xor_sync(0xffffffffu, den, off);
            if (le == 0) den_s[vloc] = (den != 0.0f) ? den : 1.0f;
        }
        __syncwarp();

        // -- phase 1b: scatter, one voxel at a time, full warp --
        const int ch    = lane & 15;
        const int chalf = lane >> 4;

        #pragma unroll
        for (int vi = 0; vi < 2; ++vi) {
            float* acc = A_s + (warp * 2 + vi) * A_STRIDE;
            const int ebase = vi * 16;

            unsigned int auxr[16];
            float fv[16];
            #pragma unroll
            for (int e = 0; e < 16; ++e) {
                auxr[e] = myaux[ebase + e];
                fv[e] = feats[(auxr[e] & 0x3FFFFu) * CIN + ch];
            }

            #pragma unroll
            for (int e = 0; e < 16; ++e) {
                const float4 g = myst[ebase + e];
                const float psi = g.x * fv[e];
                const int   cb  = (int)(auxr[e] >> 18);
                const float g0 = 1.0f - g.y, g1 = 1.0f - g.z, g2 = 1.0f - g.w;

                #pragma unroll
                for (int cc = 0; cc < 4; ++cc) {
                    const int c  = cc * 2 + chalf;
                    const int cz = (c >> 2) & 1;
                    const int cy = (c >> 1) & 1;
                    const int cx = c & 1;
                    const float w = (cz ? g.y : g0) * (cy ? g.z : g1) * (cx ? g.w : g2);
                    const int corner = cb + cz * 16 + cy * 4 + cx;
                    acc[corner * CIN + ch] += w * psi;
                }
            }
        }
    }

    __syncthreads();

    // ---- phase 2: k-split GEMM (R6 tiling). warp w owns k in [w*128, (w+1)*128).
    //      lane = vq(0..3) + 4*cq(0..7); tile: voxels {vq, vq+4, vq+8},
    //      couts {4cq..4cq+3}. A from smem, W via LDG (L2-resident). ----
    {
        const int kbase = warp * 128;
        const int vq    = lane & 3;
        const int cq    = lane >> 2;
        const float* Wp = Wg + kbase * COUT + cq * 4;

        float acc[3][4];
        #pragma unroll
        for (int i = 0; i < 3; ++i)
            #pragma unroll
            for (int j = 0; j < 4; ++j) acc[i][j] = 0.f;

        float4 af[2][3], wf[2][4];

        #pragma unroll
        for (int i = 0; i < 3; ++i)
            af[0][i] = *reinterpret_cast<const float4*>(A_s + (vq + 4 * i) * A_STRIDE + kbase);
        #pragma unroll
        for (int j = 0; j < 4; ++j)
            wf[0][j] = *reinterpret_cast<const float4*>(Wp + j * COUT);

        #pragma unroll 2
        for (int kc = 0; kc < 32; ++kc) {
            const int cur = kc & 1;
            const int nxt = cur ^ 1;
            if (kc < 31) {
                const int koff = (kc + 1) * 4;
                #pragma unroll
                for (int i = 0; i < 3; ++i)
                    af[nxt][i] = *reinterpret_cast<const float4*>(A_s + (vq + 4 * i) * A_STRIDE + kbase + koff);
                #pragma unroll
                for (int j = 0; j < 4; ++j)
                    wf[nxt][j] = *reinterpret_cast<const float4*>(Wp + (koff + j) * COUT);
            }
            #pragma unroll
            for (int i = 0; i < 3; ++i) {
                const float4 a = af[cur][i];
                acc[i][0] = fmaf(a.x, wf[cur][0].x, acc[i][0]);
                acc[i][1] = fmaf(a.x, wf[cur][0].y, acc[i][1]);
                acc[i][2] = fmaf(a.x, wf[cur][0].z, acc[i][2]);
                acc[i][3] = fmaf(a.x, wf[cur][0].w, acc[i][3]);
                acc[i][0] = fmaf(a.y, wf[cur][1].x, acc[i][0]);
                acc[i][1] = fmaf(a.y, wf[cur][1].y, acc[i][1]);
                acc[i][2] = fmaf(a.y, wf[cur][1].z, acc[i][2]);
                acc[i][3] = fmaf(a.y, wf[cur][1].w, acc[i][3]);
                acc[i][0] = fmaf(a.z, wf[cur][2].x, acc[i][0]);
                acc[i][1] = fmaf(a.z, wf[cur][2].y, acc[i][1]);
                acc[i][2] = fmaf(a.z, wf[cur][2].z, acc[i][2]);
                acc[i][3] = fmaf(a.z, wf[cur][2].w, acc[i][3]);
                acc[i][0] = fmaf(a.w, wf[cur][3].x, acc[i][0]);
                acc[i][1] = fmaf(a.w, wf[cur][3].y, acc[i][1]);
                acc[i][2] = fmaf(a.w, wf[cur][3].z, acc[i][2]);
                acc[i][3] = fmaf(a.w, wf[cur][3].w, acc[i][3]);
            }
        }

        // store per-warp partials: P_s[warp][v][c]
        #pragma unroll
        for (int i = 0; i < 3; ++i) {
            const int vv = vq + 4 * i;
            *reinterpret_cast<float4*>(P_s + (warp * VPB + vv) * COUT + cq * 4) =
                make_float4(acc[i][0], acc[i][1], acc[i][2], acc[i][3]);
        }
    }

    __syncthreads();

    // ---- reduce 8 partials, normalize, bias, relu, store ----
    {
        const int vv = tid >> 4;          // 0..15 (12..15 inactive)
        const int c0 = (tid & 15) * 2;    // cout pair
        if (vv < VPB) {
            float s0 = 0.f, s1 = 0.f;
            #pragma unroll
            for (int w = 0; w < 8; ++w) {
                const float2 p = *reinterpret_cast<const float2*>(P_s + (w * VPB + vv) * COUT + c0);
                s0 += p.x;
                s1 += p.y;
            }
            const int vg = blockIdx.x * VPB + vv;
            if (vg < n_out) {
                const float inv_den = 1.0f / den_s[vv];
                float y0 = s0 * inv_den + bias[c0 + 0];
                float y1 = s1 * inv_den + bias[c0 + 1];
                float2 r;
                r.x = fmaxf(y0, 0.0f);
                r.y = fmaxf(y1, 0.0f);
                *reinterpret_cast<float2*>(out + vg * COUT + c0) = r;
            }
        }
    }
}

extern "C" void kernel_launch(void* const* d_in, const int* in_sizes, int n_in,
                              void* d_out, int out_size)
{
    const float* feats        = (const float*)d_in[0];
    const float* inp_points   = (const float*)d_in[1];
    const float* out_points   = (const float*)d_in[2];
    const float* out_extents  = (const float*)d_in[3];
    const float* scale_compat = (const float*)d_in[4];
    const float* nbr_dist     = (const float*)d_in[5];
    const int*   nbr_idx      = (const int*)d_in[6];
    const int*   row_splits   = (const int*)d_in[7];
    const float* Wg           = (const float*)d_in[8];
    const float* bias         = (const float*)d_in[9];
    float*       out          = (float*)d_out;

    const int n_out   = in_sizes[7] - 1;
    const int n_edges = in_sizes[6];

    const size_t smem_bytes = SMEM_FLOATS * sizeof(float);
    cudaFuncSetAttribute(cconv_kernel,
                         cudaFuncAttributeMaxDynamicSharedMemorySize,
                         (int)smem_bytes);

    const int grid = (n_out + VPB - 1) / VPB;
    cconv_kernel<<<grid, THREADS, smem_bytes>>>(
        feats, inp_points, out_points, out_extents, scale_compat,
        nbr_dist, nbr_idx, row_splits, Wg, bias, out, n_out, n_edges);
}

// round 14
// speedup vs baseline: 2.0006x; 1.7800x over previous
#include <cuda_runtime.h>
#include <math.h>
#include <stdint.h>

#define CIN      16
#define COUT     32
#define KDIM     1024             // 64 taps * 16 cin
#define VPB      16
#define THREADS  256
#define A_STRIDE 1028

// B fragments: 128 k-steps x 4 n-tiles x 32 lanes x {b0,b1} (tf32 bits)
__device__ uint2 g_wf[128 * 4 * 32];

// dynamic smem layout:
//  A_s   : VPB * A_STRIDE floats            (65792 B)
//  P_s   : 8 * VPB * COUT floats            (16384 B)
//  St4_s : 8 warps * 32 edges * float4      ( 4096 B)
//  Aux_s : 8 warps * 32 edges * uint        ( 1024 B)
//  den_s : VPB floats                       (   64 B)
#define SMEM_FLOATS (VPB * A_STRIDE + 8 * VPB * COUT + 8 * 32 * 4 + 8 * 32 + VPB)

extern __shared__ float smem[];

__device__ __forceinline__ uint32_t to_tf32(float x) {
    uint32_t u;
    asm("cvt.rna.tf32.f32 %0, %1;" : "=r"(u) : "f"(x));
    return u;
}

// ================= kernel 0: pack W into tf32 B-fragments =================
// fragment (s, t, lane): b0 = W[8s + lane%4][8t + lane/4], b1 = W[8s+4+lane%4][8t + lane/4]
__global__ void wt_kernel(const float* __restrict__ Wg) {
    const int idx = blockIdx.x * 256 + threadIdx.x;
    if (idx >= 128 * 4 * 32) return;
    const int lane = idx & 31;
    const int t    = (idx >> 5) & 3;
    const int s    = idx >> 7;
    const int g    = lane >> 2;
    const int tg   = lane & 3;
    const float v0 = Wg[(s * 8 + tg) * COUT + t * 8 + g];
    const float v1 = Wg[(s * 8 + 4 + tg) * COUT + t * 8 + g];
    g_wf[idx] = make_uint2(to_tf32(v0), to_tf32(v1));
}

// ================= main fused kernel =================
__global__ void __launch_bounds__(THREADS, 2)
cconv_kernel(const float* __restrict__ feats,
             const float* __restrict__ inp_points,
             const float* __restrict__ out_points,
             const float* __restrict__ out_extents,
             const float* __restrict__ scale_compat,
             const float* __restrict__ nbr_dist,
             const int*   __restrict__ nbr_idx,
             const int*   __restrict__ row_splits,
             const float* __restrict__ bias,
             float*       __restrict__ out,
             int n_out, int n_edges)
{
    float*  A_s   = smem;
    float*  P_s   = A_s + VPB * A_STRIDE;
    float4* St4_s = reinterpret_cast<float4*>(P_s + 8 * VPB * COUT);
    unsigned int* Aux_s = reinterpret_cast<unsigned int*>(P_s + 8 * VPB * COUT + 8 * 32 * 4);
    float*  den_s = reinterpret_cast<float*>(Aux_s + 8 * 32);

    const int tid  = threadIdx.x;
    const int warp = tid >> 5;
    const int lane = tid & 31;

    float4*       myst  = St4_s + warp * 32;
    unsigned int* myaux = Aux_s + warp * 32;

    // ---- zero both acc rows owned by this warp ----
    {
        float4* acc4 = reinterpret_cast<float4*>(A_s + (warp * 2) * A_STRIDE);
        #pragma unroll
        for (int i = 0; i < 16; ++i)
            acc4[lane + i * 32] = make_float4(0.f, 0.f, 0.f, 0.f);
        if (lane < 8) (A_s + (warp * 2) * A_STRIDE)[2048 + lane] = 0.f;
    }

    // ---- phase 1a: geometry for BOTH voxels in parallel (half-warp each) ----
    const int vhalf = lane >> 4;
    const int le    = lane & 15;
    const int vloc  = warp * 2 + vhalf;
    const int v     = blockIdx.x * VPB + vloc;

    float imp_l = 0.f, f0_l = 0.f, f1_l = 0.f, f2_l = 0.f;
    unsigned int aux_l = 0;
    {
        int e0 = 0, cnt = 0;
        if (v < n_out) {
            e0  = row_splits[v];
            cnt = row_splits[v + 1] - e0;
        }
        const bool act = (le < cnt);
        if (v < n_out) {
            const float ox = out_points[v * 3 + 0];
            const float oy = out_points[v * 3 + 1];
            const float oz = out_points[v * 3 + 2];
            const float inv_r = 2.0f / out_extents[v];

            int e = e0 + le;
            if (e >= n_edges) e = n_edges - 1;

            const float sc = scale_compat[e];
            const float d  = nbr_dist[e];
            float omr = 1.0f - d;
            float w6  = omr * omr * omr;
            w6 = fminf(fmaxf(w6, 0.0f), 1.0f);

            const int nb = nbr_idx[e];
            const float rx = (inp_points[nb * 3 + 0] - ox) * inv_r;
            const float ry = (inp_points[nb * 3 + 1] - oy) * inv_r;
            const float rz = (inp_points[nb * 3 + 2] - oz) * inv_r;

            const float l2   = sqrtf(rx * rx + ry * ry + rz * rz);
            const float linf = fmaxf(fabsf(rx), fmaxf(fabsf(ry), fabsf(rz)));
            const float s    = (linf > 0.0f) ? (l2 / fmaxf(linf, 1e-12f)) : 0.0f;

            const float q0 = fminf(fmaxf(rx * s, -1.0f), 1.0f);
            const float q1 = fminf(fmaxf(ry * s, -1.0f), 1.0f);
            const float q2 = fminf(fmaxf(rz * s, -1.0f), 1.0f);

            const float t0 = (q0 + 1.0f) * 1.5f;
            const float t1 = (q1 + 1.0f) * 1.5f;
            const float t2 = (q2 + 1.0f) * 1.5f;

            const float fl0 = fminf(fmaxf(floorf(t0), 0.0f), 2.0f);
            const float fl1 = fminf(fmaxf(floorf(t1), 0.0f), 2.0f);
            const float fl2 = fminf(fmaxf(floorf(t2), 0.0f), 2.0f);
            f0_l = t0 - fl0;
            f1_l = t1 - fl1;
            f2_l = t2 - fl2;
            const int cb = (((int)fl0) * 4 + (int)fl1) * 4 + (int)fl2;

            imp_l = act ? (sc * w6) : 0.f;
            aux_l = ((unsigned int)cb << 18) | (unsigned int)nb;
        }
    }
    myst[lane]  = make_float4(imp_l, f0_l, f1_l, f2_l);
    myaux[lane] = aux_l;

    {
        float den = imp_l;
        #pragma unroll
        for (int off = 8; off > 0; off >>= 1)
            den += __shfl_xor_sync(0xffffffffu, den, off);
        if (le == 0) den_s[vloc] = (den != 0.0f) ? den : 1.0f;
    }
    __syncwarp();

    // ---- phase 1b: scatter, one voxel at a time, full warp ----
    const int ch    = lane & 15;
    const int chalf = lane >> 4;

    #pragma unroll
    for (int vi = 0; vi < 2; ++vi) {
        float* acc = A_s + (warp * 2 + vi) * A_STRIDE;
        const int ebase = vi * 16;

        unsigned int auxr[16];
        float fv[16];
        #pragma unroll
        for (int e = 0; e < 16; ++e) {
            auxr[e] = myaux[ebase + e];
            fv[e] = feats[(auxr[e] & 0x3FFFFu) * CIN + ch];
        }

        #pragma unroll
        for (int e = 0; e < 16; ++e) {
            const float4 g = myst[ebase + e];
            const float psi = g.x * fv[e];
            const int   cb  = (int)(auxr[e] >> 18);
            const float g0 = 1.0f - g.y, g1 = 1.0f - g.z, g2 = 1.0f - g.w;

            #pragma unroll
            for (int cc = 0; cc < 4; ++cc) {
                const int c  = cc * 2 + chalf;
                const int cz = (c >> 2) & 1;
                const int cy = (c >> 1) & 1;
                const int cx = c & 1;
                const float w = (cz ? g.y : g0) * (cy ? g.z : g1) * (cx ? g.w : g2);
                const int corner = cb + cz * 16 + cy * 4 + cx;
                acc[corner * CIN + ch] += w * psi;
            }
        }
    }

    __syncthreads();

    // ---- phase 2: k-split tf32 MMA. warp w owns k in [w*128, (w+1)*128)
    //      = 16 k-steps of 8. C[16x32] per warp partial via m16n8k8. ----
    {
        const int g  = lane >> 2;     // group 0..7
        const int tg = lane & 3;      // thread-in-group

        float c[4][4];
        #pragma unroll
        for (int t = 0; t < 4; ++t)
            #pragma unroll
            for (int j = 0; j < 4; ++j) c[t][j] = 0.f;

        const float* Ar0 = A_s + g * A_STRIDE;
        const float* Ar1 = A_s + (g + 8) * A_STRIDE;
        const uint2* bwp = g_wf + (warp * 16) * 4 * 32 + lane;

        #pragma unroll 4
        for (int sl = 0; sl < 16; ++sl) {
            const int k0 = warp * 128 + sl * 8 + tg;
            const uint32_t a0 = to_tf32(Ar0[k0]);
            const uint32_t a1 = to_tf32(Ar1[k0]);
            const uint32_t a2 = to_tf32(Ar0[k0 + 4]);
            const uint32_t a3 = to_tf32(Ar1[k0 + 4]);

            #pragma unroll
            for (int t = 0; t < 4; ++t) {
                const uint2 b = bwp[(sl * 4 + t) * 32];
                asm volatile(
                    "mma.sync.aligned.m16n8k8.row.col.f32.tf32.tf32.f32 "
                    "{%0,%1,%2,%3}, {%4,%5,%6,%7}, {%8,%9}, {%0,%1,%2,%3};"
                    : "+f"(c[t][0]), "+f"(c[t][1]), "+f"(c[t][2]), "+f"(c[t][3])
                    : "r"(a0), "r"(a1), "r"(a2), "r"(a3), "r"(b.x), "r"(b.y));
            }
        }

        // store partials: P_s[(warp*VPB + v)*COUT + cout]
        const int colb = tg * 2;
        #pragma unroll
        for (int t = 0; t < 4; ++t) {
            *reinterpret_cast<float2*>(P_s + (warp * VPB + g) * COUT + t * 8 + colb) =
                make_float2(c[t][0], c[t][1]);
            *reinterpret_cast<float2*>(P_s + (warp * VPB + g + 8) * COUT + t * 8 + colb) =
                make_float2(c[t][2], c[t][3]);
        }
    }

    __syncthreads();

    // ---- reduce 8 partials, normalize, bias, relu, store ----
    {
        const int vv = tid >> 4;          // 0..15
        const int c0 = (tid & 15) * 2;    // cout pair
        float s0 = 0.f, s1 = 0.f;
        #pragma unroll
        for (int w = 0; w < 8; ++w) {
            const float2 p = *reinterpret_cast<const float2*>(P_s + (w * VPB + vv) * COUT + c0);
            s0 += p.x;
            s1 += p.y;
        }
        const int vg = blockIdx.x * VPB + vv;
        if (vg < n_out) {
            const float inv_den = 1.0f / den_s[vv];
            float y0 = s0 * inv_den + bias[c0 + 0];
            float y1 = s1 * inv_den + bias[c0 + 1];
            float2 r;
            r.x = fmaxf(y0, 0.0f);
            r.y = fmaxf(y1, 0.0f);
            *reinterpret_cast<float2*>(out + vg * COUT + c0) = r;
        }
    }
}

extern "C" void kernel_launch(void* const* d_in, const int* in_sizes, int n_in,
                              void* d_out, int out_size)
{
    const float* feats        = (const float*)d_in[0];
    const float* inp_points   = (const float*)d_in[1];
    const float* out_points   = (const float*)d_in[2];
    const float* out_extents  = (const float*)d_in[3];
    const float* scale_compat = (const float*)d_in[4];
    const float* nbr_dist     = (const float*)d_in[5];
    const int*   nbr_idx      = (const int*)d_in[6];
    const int*   row_splits   = (const int*)d_in[7];
    const float* Wg           = (const float*)d_in[8];
    const float* bias         = (const float*)d_in[9];
    float*       out          = (float*)d_out;

    const int n_out   = in_sizes[7] - 1;
    const int n_edges = in_sizes[6];

    const size_t smem_bytes = SMEM_FLOATS * sizeof(float);
    cudaFuncSetAttribute(cconv_kernel,
                         cudaFuncAttributeMaxDynamicSharedMemorySize,
                         (int)smem_bytes);

    wt_kernel<<<(128 * 4 * 32 + 255) / 256, 256>>>(Wg);

    const int grid = (n_out + VPB - 1) / VPB;
    cconv_kernel<<<grid, THREADS, smem_bytes>>>(
        feats, inp_points, out_points, out_extents, scale_compat,
        nbr_dist, nbr_idx, row_splits, bias, out, n_out, n_edges);
}

// round 15
// speedup vs baseline: 2.0253x; 1.0124x over previous
#include <cuda_runtime.h>
#include <math.h>
#include <stdint.h>

#define CIN      16
#define COUT     32
#define KDIM     1024             // 64 taps * 16 cin
#define VPB      16
#define THREADS  256
#define A_STRIDE 1028

// B fragments: 128 k-steps x 4 n-tiles x 32 lanes x {b0,b1} (tf32 bits)
__device__ uint2 g_wf[128 * 4 * 32];

// dynamic smem layout (bytes):
//  A_s : VPB * A_STRIDE floats                     (65792)
//  U   : union { phase1: St4(4096)+Aux(1024) ;
//                phase2: P = 4*VPB*COUT floats }   ( 8192)
//  den : VPB floats                                (   64)
#define SMEM_FLOATS (VPB * A_STRIDE + 4 * VPB * COUT + VPB)

extern __shared__ float smem[];

__device__ __forceinline__ uint32_t to_tf32(float x) {
    uint32_t u;
    asm("cvt.rna.tf32.f32 %0, %1;" : "=r"(u) : "f"(x));
    return u;
}

// ================= kernel 0: pack W into tf32 B-fragments =================
// fragment (s, t, lane): b0 = W[8s + lane%4][8t + lane/4], b1 = W[8s+4+lane%4][8t + lane/4]
__global__ void wt_kernel(const float* __restrict__ Wg) {
    const int idx = blockIdx.x * 256 + threadIdx.x;
    if (idx >= 128 * 4 * 32) return;
    const int lane = idx & 31;
    const int t    = (idx >> 5) & 3;
    const int s    = idx >> 7;
    const int g    = lane >> 2;
    const int tg   = lane & 3;
    const float v0 = Wg[(s * 8 + tg) * COUT + t * 8 + g];
    const float v1 = Wg[(s * 8 + 4 + tg) * COUT + t * 8 + g];
    g_wf[idx] = make_uint2(to_tf32(v0), to_tf32(v1));
}

// ================= main fused kernel =================
__global__ void __launch_bounds__(THREADS, 3)
cconv_kernel(const float* __restrict__ feats,
             const float* __restrict__ inp_points,
             const float* __restrict__ out_points,
             const float* __restrict__ out_extents,
             const float* __restrict__ scale_compat,
             const float* __restrict__ nbr_dist,
             const int*   __restrict__ nbr_idx,
             const int*   __restrict__ row_splits,
             const float* __restrict__ bias,
             float*       __restrict__ out,
             int n_out, int n_edges)
{
    float*  A_s   = smem;
    float*  U_s   = A_s + VPB * A_STRIDE;                       // union region
    float*  P_s   = U_s;                                        // phase-2 partials
    float4* St4_s = reinterpret_cast<float4*>(U_s);             // phase-1 staging
    unsigned int* Aux_s = reinterpret_cast<unsigned int*>(U_s + 8 * 32 * 4);
    float*  den_s = U_s + 4 * VPB * COUT;

    const int tid  = threadIdx.x;
    const int warp = tid >> 5;
    const int lane = tid & 31;

    float4*       myst  = St4_s + warp * 32;
    unsigned int* myaux = Aux_s + warp * 32;

    // ---- zero both acc rows owned by this warp ----
    {
        float4* acc4 = reinterpret_cast<float4*>(A_s + (warp * 2) * A_STRIDE);
        #pragma unroll
        for (int i = 0; i < 16; ++i)
            acc4[lane + i * 32] = make_float4(0.f, 0.f, 0.f, 0.f);
        if (lane < 8) (A_s + (warp * 2) * A_STRIDE)[2048 + lane] = 0.f;
    }

    // ---- phase 1a: geometry for BOTH voxels in parallel (half-warp each) ----
    const int vhalf = lane >> 4;
    const int le    = lane & 15;
    const int vloc  = warp * 2 + vhalf;
    const int v     = blockIdx.x * VPB + vloc;

    float imp_l = 0.f, f0_l = 0.f, f1_l = 0.f, f2_l = 0.f;
    unsigned int aux_l = 0;
    {
        int e0 = 0, cnt = 0;
        if (v < n_out) {
            e0  = row_splits[v];
            cnt = row_splits[v + 1] - e0;
        }
        const bool act = (le < cnt);
        if (v < n_out) {
            const float ox = out_points[v * 3 + 0];
            const float oy = out_points[v * 3 + 1];
            const float oz = out_points[v * 3 + 2];
            const float inv_r = 2.0f / out_extents[v];

            int e = e0 + le;
            if (e >= n_edges) e = n_edges - 1;

            const float sc = scale_compat[e];
            const float d  = nbr_dist[e];
            float omr = 1.0f - d;
            float w6  = omr * omr * omr;
            w6 = fminf(fmaxf(w6, 0.0f), 1.0f);

            const int nb = nbr_idx[e];
            const float rx = (inp_points[nb * 3 + 0] - ox) * inv_r;
            const float ry = (inp_points[nb * 3 + 1] - oy) * inv_r;
            const float rz = (inp_points[nb * 3 + 2] - oz) * inv_r;

            const float l2   = sqrtf(rx * rx + ry * ry + rz * rz);
            const float linf = fmaxf(fabsf(rx), fmaxf(fabsf(ry), fabsf(rz)));
            const float s    = (linf > 0.0f) ? (l2 / fmaxf(linf, 1e-12f)) : 0.0f;

            const float q0 = fminf(fmaxf(rx * s, -1.0f), 1.0f);
            const float q1 = fminf(fmaxf(ry * s, -1.0f), 1.0f);
            const float q2 = fminf(fmaxf(rz * s, -1.0f), 1.0f);

            const float t0 = (q0 + 1.0f) * 1.5f;
            const float t1 = (q1 + 1.0f) * 1.5f;
            const float t2 = (q2 + 1.0f) * 1.5f;

            const float fl0 = fminf(fmaxf(floorf(t0), 0.0f), 2.0f);
            const float fl1 = fminf(fmaxf(floorf(t1), 0.0f), 2.0f);
            const float fl2 = fminf(fmaxf(floorf(t2), 0.0f), 2.0f);
            f0_l = t0 - fl0;
            f1_l = t1 - fl1;
            f2_l = t2 - fl2;
            const int cb = (((int)fl0) * 4 + (int)fl1) * 4 + (int)fl2;

            imp_l = act ? (sc * w6) : 0.f;
            aux_l = ((unsigned int)cb << 18) | (unsigned int)nb;
        }
    }
    myst[lane]  = make_float4(imp_l, f0_l, f1_l, f2_l);
    myaux[lane] = aux_l;

    {
        float den = imp_l;
        #pragma unroll
        for (int off = 8; off > 0; off >>= 1)
            den += __shfl_xor_sync(0xffffffffu, den, off);
        if (le == 0) den_s[vloc] = (den != 0.0f) ? den : 1.0f;
    }
    __syncwarp();

    // ---- phase 1b: scatter, one voxel at a time, full warp ----
    const int ch    = lane & 15;
    const int chalf = lane >> 4;

    #pragma unroll
    for (int vi = 0; vi < 2; ++vi) {
        float* acc = A_s + (warp * 2 + vi) * A_STRIDE;
        const int ebase = vi * 16;

        unsigned int auxr[16];
        float fv[16];
        #pragma unroll
        for (int e = 0; e < 16; ++e) {
            auxr[e] = myaux[ebase + e];
            fv[e] = feats[(auxr[e] & 0x3FFFFu) * CIN + ch];
        }

        #pragma unroll
        for (int e = 0; e < 16; ++e) {
            const float4 g = myst[ebase + e];
            const float psi = g.x * fv[e];
            const int   cb  = (int)(auxr[e] >> 18);
            const float g0 = 1.0f - g.y, g1 = 1.0f - g.z, g2 = 1.0f - g.w;

            #pragma unroll
            for (int cc = 0; cc < 4; ++cc) {
                const int c  = cc * 2 + chalf;
                const int cz = (c >> 2) & 1;
                const int cy = (c >> 1) & 1;
                const int cx = c & 1;
                const float w = (cz ? g.y : g0) * (cy ? g.z : g1) * (cx ? g.w : g2);
                const int corner = cb + cz * 16 + cy * 4 + cx;
                acc[corner * CIN + ch] += w * psi;
            }
        }
    }

    __syncthreads();   // phase-1 done everywhere; St4/Aux dead; P_s may be written

    // ---- phase 2: k-split tf32 MMA. warp w owns k in [w*128, (w+1)*128)
    //      = 16 k-steps of 8. C[16x32] per warp partial via m16n8k8. ----
    float c[4][4];
    {
        const int g  = lane >> 2;     // group 0..7
        const int tg = lane & 3;      // thread-in-group

        #pragma unroll
        for (int t = 0; t < 4; ++t)
            #pragma unroll
            for (int j = 0; j < 4; ++j) c[t][j] = 0.f;

        const float* Ar0 = A_s + g * A_STRIDE;
        const float* Ar1 = A_s + (g + 8) * A_STRIDE;
        const uint2* bwp = g_wf + (warp * 16) * 4 * 32 + lane;

        #pragma unroll 4
        for (int sl = 0; sl < 16; ++sl) {
            const int k0 = warp * 128 + sl * 8 + tg;
            const uint32_t a0 = to_tf32(Ar0[k0]);
            const uint32_t a1 = to_tf32(Ar1[k0]);
            const uint32_t a2 = to_tf32(Ar0[k0 + 4]);
            const uint32_t a3 = to_tf32(Ar1[k0 + 4]);

            #pragma unroll
            for (int t = 0; t < 4; ++t) {
                const uint2 b = bwp[(sl * 4 + t) * 32];
                asm volatile(
                    "mma.sync.aligned.m16n8k8.row.col.f32.tf32.tf32.f32 "
                    "{%0,%1,%2,%3}, {%4,%5,%6,%7}, {%8,%9}, {%0,%1,%2,%3};"
                    : "+f"(c[t][0]), "+f"(c[t][1]), "+f"(c[t][2]), "+f"(c[t][3])
                    : "r"(a0), "r"(a1), "r"(a2), "r"(a3), "r"(b.x), "r"(b.y));
            }
        }
    }

    // ---- partial combine: warps 0-3 store, warps 4-7 add in place ----
    {
        const int g    = lane >> 2;
        const int colb = (lane & 3) * 2;
        const int pw   = warp & 3;

        if (warp < 4) {
            #pragma unroll
            for (int t = 0; t < 4; ++t) {
                *reinterpret_cast<float2*>(P_s + (pw * VPB + g) * COUT + t * 8 + colb) =
                    make_float2(c[t][0], c[t][1]);
                *reinterpret_cast<float2*>(P_s + (pw * VPB + g + 8) * COUT + t * 8 + colb) =
                    make_float2(c[t][2], c[t][3]);
            }
        }
        __syncthreads();
        if (warp >= 4) {
            #pragma unroll
            for (int t = 0; t < 4; ++t) {
                float2* p0 = reinterpret_cast<float2*>(P_s + (pw * VPB + g) * COUT + t * 8 + colb);
                float2* p1 = reinterpret_cast<float2*>(P_s + (pw * VPB + g + 8) * COUT + t * 8 + colb);
                float2 v0 = *p0, v1 = *p1;
                v0.x += c[t][0]; v0.y += c[t][1];
                v1.x += c[t][2]; v1.y += c[t][3];
                *p0 = v0; *p1 = v1;
            }
        }
    }

    __syncthreads();

    // ---- reduce 4 partials, normalize, bias, relu, store ----
    {
        const int vv = tid >> 4;          // 0..15
        const int c0 = (tid & 15) * 2;    // cout pair
        float s0 = 0.f, s1 = 0.f;
        #pragma unroll
        for (int w = 0; w < 4; ++w) {
            const float2 p = *reinterpret_cast<const float2*>(P_s + (w * VPB + vv) * COUT + c0);
            s0 += p.x;
            s1 += p.y;
        }
        const int vg = blockIdx.x * VPB + vv;
        if (vg < n_out) {
            const float inv_den = 1.0f / den_s[vv];
            float y0 = s0 * inv_den + bias[c0 + 0];
            float y1 = s1 * inv_den + bias[c0 + 1];
            float2 r;
            r.x = fmaxf(y0, 0.0f);
            r.y = fmaxf(y1, 0.0f);
            *reinterpret_cast<float2*>(out + vg * COUT + c0) = r;
        }
    }
}

extern "C" void kernel_launch(void* const* d_in, const int* in_sizes, int n_in,
                              void* d_out, int out_size)
{
    const float* feats        = (const float*)d_in[0];
    const float* inp_points   = (const float*)d_in[1];
    const float* out_points   = (const float*)d_in[2];
    const float* out_extents  = (const float*)d_in[3];
    const float* scale_compat = (const float*)d_in[4];
    const float* nbr_dist     = (const float*)d_in[5];
    const int*   nbr_idx      = (const int*)d_in[6];
    const int*   row_splits   = (const int*)d_in[7];
    const float* Wg           = (const float*)d_in[8];
    const float* bias         = (const float*)d_in[9];
    float*       out          = (float*)d_out;

    const int n_out   = in_sizes[7] - 1;
    const int n_edges = in_sizes[6];

    const size_t smem_bytes = SMEM_FLOATS * sizeof(float);
    cudaFuncSetAttribute(cconv_kernel,
                         cudaFuncAttributeMaxDynamicSharedMemorySize,
                         (int)smem_bytes);

    wt_kernel<<<(128 * 4 * 32 + 255) / 256, 256>>>(Wg);

    const int grid = (n_out + VPB - 1) / VPB;
    cconv_kernel<<<grid, THREADS, smem_bytes>>>(
        feats, inp_points, out_points, out_extents, scale_compat,
        nbr_dist, nbr_idx, row_splits, bias, out, n_out, n_edges);
}

// round 16
// speedup vs baseline: 2.0261x; 1.0004x over previous
#include <cuda_runtime.h>
#include <math.h>
#include <stdint.h>

#define CIN      16
#define COUT     32
#define KDIM     1024             // 64 taps * 16 cin
#define VPB      16
#define THREADS  256
#define A_STRIDE 1028

// B fragments: 128 k-steps x 4 n-tiles x 32 lanes x {b0,b1} (tf32 bits)
__device__ uint2 g_wf[128 * 4 * 32];

// dynamic smem layout (bytes):
//  A_s : VPB * A_STRIDE floats                     (65792)
//  U   : union { phase1: St4(4096)+Aux(1024) ;
//                phase2: P = 4*VPB*COUT floats }   ( 8192)
//  den : VPB floats                                (   64)
#define SMEM_FLOATS (VPB * A_STRIDE + 4 * VPB * COUT + VPB)

extern __shared__ float smem[];

__device__ __forceinline__ uint32_t to_tf32(float x) {
    uint32_t u;
    asm("cvt.rna.tf32.f32 %0, %1;" : "=r"(u) : "f"(x));
    return u;
}

// ================= kernel 0: pack W into tf32 B-fragments =================
__global__ void wt_kernel(const float* __restrict__ Wg) {
    const int idx = blockIdx.x * 256 + threadIdx.x;
    if (idx >= 128 * 4 * 32) return;
    const int lane = idx & 31;
    const int t    = (idx >> 5) & 3;
    const int s    = idx >> 7;
    const int g    = lane >> 2;
    const int tg   = lane & 3;
    const float v0 = Wg[(s * 8 + tg) * COUT + t * 8 + g];
    const float v1 = Wg[(s * 8 + 4 + tg) * COUT + t * 8 + g];
    g_wf[idx] = make_uint2(to_tf32(v0), to_tf32(v1));
}

// ================= main fused kernel =================
__global__ void __launch_bounds__(THREADS, 3)
cconv_kernel(const float* __restrict__ feats,
             const float* __restrict__ inp_points,
             const float* __restrict__ out_points,
             const float* __restrict__ out_extents,
             const float* __restrict__ scale_compat,
             const float* __restrict__ nbr_dist,
             const int*   __restrict__ nbr_idx,
             const int*   __restrict__ row_splits,
             const float* __restrict__ bias,
             float*       __restrict__ out,
             int n_out, int n_edges)
{
    float*  A_s   = smem;
    float*  U_s   = A_s + VPB * A_STRIDE;                       // union region
    float*  P_s   = U_s;                                        // phase-2 partials
    float4* St4_s = reinterpret_cast<float4*>(U_s);             // phase-1 staging
    unsigned int* Aux_s = reinterpret_cast<unsigned int*>(U_s + 8 * 32 * 4);
    float*  den_s = U_s + 4 * VPB * COUT;

    const int tid  = threadIdx.x;
    const int warp = tid >> 5;
    const int lane = tid & 31;

    float4*       myst  = St4_s + warp * 32;
    unsigned int* myaux = Aux_s + warp * 32;

    // ---- zero both acc rows owned by this warp ----
    {
        float4* acc4 = reinterpret_cast<float4*>(A_s + (warp * 2) * A_STRIDE);
        #pragma unroll
        for (int i = 0; i < 16; ++i)
            acc4[lane + i * 32] = make_float4(0.f, 0.f, 0.f, 0.f);
        if (lane < 8) (A_s + (warp * 2) * A_STRIDE)[2048 + lane] = 0.f;
    }

    // ---- phase 1a: geometry for BOTH voxels in parallel (half-warp each) ----
    const int vhalf = lane >> 4;
    const int le    = lane & 15;
    const int vloc  = warp * 2 + vhalf;
    const int v     = blockIdx.x * VPB + vloc;

    float imp_l = 0.f, f0_l = 0.f, f1_l = 0.f, f2_l = 0.f;
    unsigned int aux_l = 0;
    {
        int e0 = 0, cnt = 0;
        if (v < n_out) {
            e0  = row_splits[v];
            cnt = row_splits[v + 1] - e0;
        }
        const bool act = (le < cnt);
        if (v < n_out) {
            const float ox = out_points[v * 3 + 0];
            const float oy = out_points[v * 3 + 1];
            const float oz = out_points[v * 3 + 2];
            const float inv_r = 2.0f / out_extents[v];

            int e = e0 + le;
            if (e >= n_edges) e = n_edges - 1;

            const float sc = scale_compat[e];
            const float d  = nbr_dist[e];
            float omr = 1.0f - d;
            float w6  = omr * omr * omr;
            w6 = fminf(fmaxf(w6, 0.0f), 1.0f);

            const int nb = nbr_idx[e];
            const float rx = (inp_points[nb * 3 + 0] - ox) * inv_r;
            const float ry = (inp_points[nb * 3 + 1] - oy) * inv_r;
            const float rz = (inp_points[nb * 3 + 2] - oz) * inv_r;

            const float l2   = sqrtf(rx * rx + ry * ry + rz * rz);
            const float linf = fmaxf(fabsf(rx), fmaxf(fabsf(ry), fabsf(rz)));
            const float s    = (linf > 0.0f) ? (l2 / fmaxf(linf, 1e-12f)) : 0.0f;

            const float q0 = fminf(fmaxf(rx * s, -1.0f), 1.0f);
            const float q1 = fminf(fmaxf(ry * s, -1.0f), 1.0f);
            const float q2 = fminf(fmaxf(rz * s, -1.0f), 1.0f);

            const float t0 = (q0 + 1.0f) * 1.5f;
            const float t1 = (q1 + 1.0f) * 1.5f;
            const float t2 = (q2 + 1.0f) * 1.5f;

            const float fl0 = fminf(fmaxf(floorf(t0), 0.0f), 2.0f);
            const float fl1 = fminf(fmaxf(floorf(t1), 0.0f), 2.0f);
            const float fl2 = fminf(fmaxf(floorf(t2), 0.0f), 2.0f);
            f0_l = t0 - fl0;
            f1_l = t1 - fl1;
            f2_l = t2 - fl2;
            const int cb = (((int)fl0) * 4 + (int)fl1) * 4 + (int)fl2;

            imp_l = act ? (sc * w6) : 0.f;
            aux_l = ((unsigned int)cb << 18) | (unsigned int)nb;
        }
    }
    myst[lane]  = make_float4(imp_l, f0_l, f1_l, f2_l);
    myaux[lane] = aux_l;

    {
        float den = imp_l;
        #pragma unroll
        for (int off = 8; off > 0; off >>= 1)
            den += __shfl_xor_sync(0xffffffffu, den, off);
        if (le == 0) den_s[vloc] = (den != 0.0f) ? den : 1.0f;
    }
    __syncwarp();

    // ---- phase 1b: scatter, BOTH voxels interleaved (2 independent chains).
    //      base = acc + cb*16 + ch + chalf*16; corners at imm float offsets
    //      {0, 64, 256, 320}; per corner one FFMA into smem. ----
    {
        const int ch    = lane & 15;
        const int chalf = lane >> 4;
        const int chb   = ch + chalf * 16;
        float* accA = A_s + (warp * 2) * A_STRIDE;
        float* accB = accA + A_STRIDE;

        #pragma unroll
        for (int hf = 0; hf < 2; ++hf) {
            unsigned int auxA[8], auxB[8];
            float fvA[8], fvB[8];
            #pragma unroll
            for (int e = 0; e < 8; ++e) {
                auxA[e] = myaux[hf * 8 + e];
                auxB[e] = myaux[16 + hf * 8 + e];
                fvA[e] = feats[(auxA[e] & 0x3FFFFu) * CIN + ch];
                fvB[e] = feats[(auxB[e] & 0x3FFFFu) * CIN + ch];
            }
            #pragma unroll
            for (int e = 0; e < 8; ++e) {
                {   // voxel A
                    const float4 g = myst[hf * 8 + e];
                    float* base = accA + (int)((auxA[e] >> 18) << 4) + chb;
                    const float g0 = 1.f - g.y, g1 = 1.f - g.z;
                    const float h2 = chalf ? g.w : (1.f - g.w);
                    const float h  = h2 * (g.x * fvA[e]);
                    const float p00 = g0  * g1,  p01 = g0  * g.z;
                    const float p10 = g.y * g1,  p11 = g.y * g.z;
                    base[0]   = fmaf(p00, h, base[0]);
                    base[64]  = fmaf(p01, h, base[64]);
                    base[256] = fmaf(p10, h, base[256]);
                    base[320] = fmaf(p11, h, base[320]);
                }
                {   // voxel B (independent chain)
                    const float4 g = myst[16 + hf * 8 + e];
                    float* base = accB + (int)((auxB[e] >> 18) << 4) + chb;
                    const float g0 = 1.f - g.y, g1 = 1.f - g.z;
                    const float h2 = chalf ? g.w : (1.f - g.w);
                    const float h  = h2 * (g.x * fvB[e]);
                    const float p00 = g0  * g1,  p01 = g0  * g.z;
                    const float p10 = g.y * g1,  p11 = g.y * g.z;
                    base[0]   = fmaf(p00, h, base[0]);
                    base[64]  = fmaf(p01, h, base[64]);
                    base[256] = fmaf(p10, h, base[256]);
                    base[320] = fmaf(p11, h, base[320]);
                }
            }
        }
    }

    __syncthreads();   // phase-1 done everywhere; St4/Aux dead; P_s may be written

    // ---- phase 2: k-split tf32 MMA (16 k-steps of 8 per warp) ----
    float c[4][4];
    {
        const int g  = lane >> 2;
        const int tg = lane & 3;

        #pragma unroll
        for (int t = 0; t < 4; ++t)
            #pragma unroll
            for (int j = 0; j < 4; ++j) c[t][j] = 0.f;

        const float* Ar0 = A_s + g * A_STRIDE;
        const float* Ar1 = A_s + (g + 8) * A_STRIDE;
        const uint2* bwp = g_wf + (warp * 16) * 4 * 32 + lane;

        #pragma unroll 4
        for (int sl = 0; sl < 16; ++sl) {
            const int k0 = warp * 128 + sl * 8 + tg;
            const uint32_t a0 = to_tf32(Ar0[k0]);
            const uint32_t a1 = to_tf32(Ar1[k0]);
            const uint32_t a2 = to_tf32(Ar0[k0 + 4]);
            const uint32_t a3 = to_tf32(Ar1[k0 + 4]);

            #pragma unroll
            for (int t = 0; t < 4; ++t) {
                const uint2 b = bwp[(sl * 4 + t) * 32];
                asm volatile(
                    "mma.sync.aligned.m16n8k8.row.col.f32.tf32.tf32.f32 "
                    "{%0,%1,%2,%3}, {%4,%5,%6,%7}, {%8,%9}, {%0,%1,%2,%3};"
                    : "+f"(c[t][0]), "+f"(c[t][1]), "+f"(c[t][2]), "+f"(c[t][3])
                    : "r"(a0), "r"(a1), "r"(a2), "r"(a3), "r"(b.x), "r"(b.y));
            }
        }
    }

    // ---- partial combine: warps 0-3 store, warps 4-7 add in place ----
    {
        const int g    = lane >> 2;
        const int colb = (lane & 3) * 2;
        const int pw   = warp & 3;

        if (warp < 4) {
            #pragma unroll
            for (int t = 0; t < 4; ++t) {
                *reinterpret_cast<float2*>(P_s + (pw * VPB + g) * COUT + t * 8 + colb) =
                    make_float2(c[t][0], c[t][1]);
                *reinterpret_cast<float2*>(P_s + (pw * VPB + g + 8) * COUT + t * 8 + colb) =
                    make_float2(c[t][2], c[t][3]);
            }
        }
        __syncthreads();
        if (warp >= 4) {
            #pragma unroll
            for (int t = 0; t < 4; ++t) {
                float2* p0 = reinterpret_cast<float2*>(P_s + (pw * VPB + g) * COUT + t * 8 + colb);
                float2* p1 = reinterpret_cast<float2*>(P_s + (pw * VPB + g + 8) * COUT + t * 8 + colb);
                float2 v0 = *p0, v1 = *p1;
                v0.x += c[t][0]; v0.y += c[t][1];
                v1.x += c[t][2]; v1.y += c[t][3];
                *p0 = v0; *p1 = v1;
            }
        }
    }

    __syncthreads();

    // ---- reduce 4 partials, normalize, bias, relu, store ----
    {
        const int vv = tid >> 4;
        const int c0 = (tid & 15) * 2;
        float s0 = 0.f, s1 = 0.f;
        #pragma unroll
        for (int w = 0; w < 4; ++w) {
            const float2 p = *reinterpret_cast<const float2*>(P_s + (w * VPB + vv) * COUT + c0);
            s0 += p.x;
            s1 += p.y;
        }
        const int vg = blockIdx.x * VPB + vv;
        if (vg < n_out) {
            const float inv_den = 1.0f / den_s[vv];
            float y0 = s0 * inv_den + bias[c0 + 0];
            float y1 = s1 * inv_den + bias[c0 + 1];
            float2 r;
            r.x = fmaxf(y0, 0.0f);
            r.y = fmaxf(y1, 0.0f);
            *reinterpret_cast<float2*>(out + vg * COUT + c0) = r;
        }
    }
}

extern "C" void kernel_launch(void* const* d_in, const int* in_sizes, int n_in,
                              void* d_out, int out_size)
{
    const float* feats        = (const float*)d_in[0];
    const float* inp_points   = (const float*)d_in[1];
    const float* out_points   = (const float*)d_in[2];
    const float* out_extents  = (const float*)d_in[3];
    const float* scale_compat = (const float*)d_in[4];
    const float* nbr_dist     = (const float*)d_in[5];
    const int*   nbr_idx      = (const int*)d_in[6];
    const int*   row_splits   = (const int*)d_in[7];
    const float* Wg           = (const float*)d_in[8];
    const float* bias         = (const float*)d_in[9];
    float*       out          = (float*)d_out;

    const int n_out   = in_sizes[7] - 1;
    const int n_edges = in_sizes[6];

    const size_t smem_bytes = SMEM_FLOATS * sizeof(float);
    cudaFuncSetAttribute(cconv_kernel,
                         cudaFuncAttributeMaxDynamicSharedMemorySize,
                         (int)smem_bytes);

    wt_kernel<<<(128 * 4 * 32 + 255) / 256, 256>>>(Wg);

    const int grid = (n_out + VPB - 1) / VPB;
    cconv_kernel<<<grid, THREADS, smem_bytes>>>(
        feats, inp_points, out_points, out_extents, scale_compat,
        nbr_dist, nbr_idx, row_splits, bias, out, n_out, n_edges);
}